// round 14
// baseline (speedup 1.0000x reference)
#include <cuda_runtime.h>

// TT-linear: y = x @ W^T + bias
//   c0: [1,32(o0),32(i0),4(r1)]  c1: [4(r1),16(o1),16(i1),4(r2)]  c2: [4(r2),16(o2),16(i2),1]
//
// Kernel 0: out = bias (broadcast fill).
// Kernel 1: grid 256 = (token-pair 64) x (i0-quarter 4); 512 thr; 2 CTAs/SM = 32 warps/SM.
//   Lane map: o2 = tid&15, z = (tid>>4)&1, o1 = tid>>5 (each warp = one o1).
//   T=2 tokens per CTA; chip fma2 = algorithmic minimum (234M), per-thread state halved
//   vs R13 (yp 16 u64, acc 8 u64) so occupancy doubles at the 64-reg cap.
//   step1: thread produces A row i1=o1 for token z (c2 loads broadcast across z).
//   step2: z splits i1 (8 each), both tokens; 8 acc chains; shfl_xor(16) combine.
//   step3: z splits o0; c0 loads broadcast. ONE __syncthreads per slice.
//   Epilogue: RED.ADD into bias-prefilled out (4 CTAs per element).

#define THREADS 512

typedef unsigned long long u64;

__device__ __forceinline__ u64 pk2(float lo, float hi) {
    u64 r;
    asm("mov.b64 %0, {%1, %2};" : "=l"(r) : "f"(lo), "f"(hi));
    return r;
}
__device__ __forceinline__ void unpk(u64 v, float& lo, float& hi) {
    asm("mov.b64 {%0, %1}, %2;" : "=f"(lo), "=f"(hi) : "l"(v));
}
__device__ __forceinline__ u64 fma2(u64 a, u64 b, u64 c) {
    u64 d;
    asm("fma.rn.f32x2 %0, %1, %2, %3;" : "=l"(d) : "l"(a), "l"(b), "l"(c));
    return d;
}
__device__ __forceinline__ float hadd(u64 v) {
    float lo, hi;
    unpk(v, lo, hi);
    return lo + hi;
}

#define XPAD 260   // sX token stride in floats (bank-decorrelating pad)

// step1: A_z[i1=o1][o2][r2] for ONE token (this thread's z), shared c2 loads.
__device__ __forceinline__ void step1_one(const float* __restrict__ Xs,
                                          float* __restrict__ Ad,
                                          const float* __restrict__ sc2,
                                          int o1, int o2)
{
    u64 a01 = 0ull, a23 = 0ull;
    #pragma unroll
    for (int ch = 0; ch < 2; ch++) {
        const float4* xq = reinterpret_cast<const float4*>(&Xs[o1 * 16 + ch * 8]);
        float4 p0 = xq[0], p1 = xq[1];
        float xs[8] = { p0.x,p0.y,p0.z,p0.w, p1.x,p1.y,p1.z,p1.w };
        #pragma unroll
        for (int j = 0; j < 8; j++) {
            const int i2 = ch * 8 + j;
            ulonglong2 c = *reinterpret_cast<const ulonglong2*>(&sc2[(i2 * 16 + o2) * 4]);
            u64 xd = pk2(xs[j], xs[j]);
            a01 = fma2(xd, c.x, a01);
            a23 = fma2(xd, c.y, a23);
        }
    }
    ulonglong2 st; st.x = a01; st.y = a23;
    *reinterpret_cast<ulonglong2*>(&Ad[(o1 * 16 + o2) * 4]) = st;
}

__global__ __launch_bounds__(THREADS, 2)
void tt_partial_kernel(const float* __restrict__ x,
                       const float* __restrict__ g0,
                       const float* __restrict__ g1,
                       const float* __restrict__ g2,
                       float* __restrict__ out)
{
    __shared__ __align__(16) float sc0[1024];          // [it 8][r1 4][o0 32]
    __shared__ __align__(16) float sc1[4096];          // [o1 16][i1 16][r1 4][r2 4]
    __shared__ __align__(16) float sc2[1024];          // [i2][o2][r2]
    __shared__ __align__(16) float sA[2][2][1024];     // [buf][tok][i1][o2][r2]
    __shared__ __align__(16) float sX[2][2][XPAD];     // [buf][tok][elem(+pad)]

    const int tid     = threadIdx.x;
    const int o2      = tid & 15;
    const int z       = (tid >> 4) & 1;
    const int o1      = tid >> 5;                      // 0..15; == warp id
    const int sid     = tid & 255;                     // staging element
    const int tz      = tid >> 8;                      // staging token
    const int pair    = blockIdx.x & 63;
    const int quarter = blockIdx.x >> 6;
    const int i0base  = quarter * 8;

    // ---- core relayout into smem (stride 512) ----
    for (int idx = tid; idx < 1024; idx += THREADS) {
        int o0 = idx & 31, r1 = (idx >> 5) & 3, it = idx >> 7;      // it = 0..7
        sc0[idx] = g0[(o0 * 32 + i0base + it) * 4 + r1];
    }
    for (int idx = tid; idx < 4096; idx += THREADS) {
        int r2 = idx & 3, r1 = (idx >> 2) & 3, i1 = (idx >> 4) & 15, o1g = idx >> 8;
        sc1[idx] = g1[((r1 * 16 + o1g) * 16 + i1) * 4 + r2];
    }
    for (int idx = tid; idx < 1024; idx += THREADS) {
        int r2 = idx & 3, o2g = (idx >> 2) & 15, i2 = idx >> 6;
        sc2[idx] = g2[(r2 * 16 + o2g) * 16 + i2];
    }

    const float* xme = x + (size_t)(2 * pair + tz) * 8192;   // this thread stages token tz
    sX[0][tz][sid] = xme[(i0base + 0) * 256 + sid];
    sX[1][tz][sid] = xme[(i0base + 1) * 256 + sid];

    u64 yp[2][8];                          // [tok][o0'-pair], own z o0-half
    #pragma unroll
    for (int t = 0; t < 2; t++)
        #pragma unroll
        for (int i = 0; i < 8; i++) yp[t][i] = 0ull;

    __syncthreads();

    // prologue: step1 for slice 0 (own token z)
    step1_one(sX[0][z], sA[0][z], sc2, o1, o2);
    float xn = xme[(i0base + 2) * 256 + sid];
    __syncthreads();

    for (int k = 0; k < 8; k++) {
        const int b = k & 1;

        // ---- step 2: B-partial over own i1-half, both tokens (8 chains) ----
        u64 acc[2][4];
        #pragma unroll
        for (int t = 0; t < 2; t++)
            #pragma unroll
            for (int r1 = 0; r1 < 4; r1++) acc[t][r1] = 0ull;

        const float* A0 = sA[b][0];
        const float* A1 = sA[b][1];
        #pragma unroll
        for (int s = 0; s < 8; s++) {
            const int i1 = z * 8 + s;
            const ulonglong2 av0 = *reinterpret_cast<const ulonglong2*>(
                &A0[(i1 * 16 + o2) * 4]);
            const ulonglong2 av1 = *reinterpret_cast<const ulonglong2*>(
                &A1[(i1 * 16 + o2) * 4]);
            const ulonglong2* cp = reinterpret_cast<const ulonglong2*>(
                &sc1[(o1 * 16 + i1) * 16]);            // per-warp: 2 bcast addrs
            #pragma unroll
            for (int r1 = 0; r1 < 4; r1++) {
                ulonglong2 c = cp[r1];
                acc[0][r1] = fma2(av0.x, c.x, acc[0][r1]);
                acc[0][r1] = fma2(av0.y, c.y, acc[0][r1]);
                acc[1][r1] = fma2(av1.x, c.x, acc[1][r1]);
                acc[1][r1] = fma2(av1.y, c.y, acc[1][r1]);
            }
        }
        // combine z-halves (partner = lane^16, same o1/o2) -> duplicated B
        u64 bd[2][4];
        #pragma unroll
        for (int t = 0; t < 2; t++)
            #pragma unroll
            for (int r1 = 0; r1 < 4; r1++) {
                float p = hadd(acc[t][r1]);
                p += __shfl_xor_sync(0xffffffffu, p, 16);
                bd[t][r1] = pk2(p, p);
            }

        // ---- step 3: own z o0-half, both tokens; c0 loads broadcast ----
        #pragma unroll
        for (int r1 = 0; r1 < 4; r1++) {
            const ulonglong2* cq = reinterpret_cast<const ulonglong2*>(
                &sc0[k * 128 + r1 * 32 + z * 16]);
            #pragma unroll
            for (int q = 0; q < 4; q++) {
                ulonglong2 c = cq[q];                  // o0' = 4q..4q+3 within half
                yp[0][2 * q]     = fma2(bd[0][r1], c.x, yp[0][2 * q]);
                yp[0][2 * q + 1] = fma2(bd[0][r1], c.y, yp[0][2 * q + 1]);
                yp[1][2 * q]     = fma2(bd[1][r1], c.x, yp[1][2 * q]);
                yp[1][2 * q + 1] = fma2(bd[1][r1], c.y, yp[1][2 * q + 1]);
            }
        }

        // ---- step 1 for slice k+1 (own token); stage slice k+2; one sync ----
        if (k < 7) {
            const int nb = (k + 1) & 1;
            step1_one(sX[nb][z], sA[nb][z], sc2, o1, o2);
            if (k < 6) {
                sX[b][tz][sid] = xn;
                if (k < 5) xn = xme[(i0base + k + 3) * 256 + sid];
            }
            __syncthreads();
        }
    }

    // ---- epilogue: RED.ADD into bias-prefilled out ----
    const int col = o1 * 16 + o2;
    #pragma unroll
    for (int t = 0; t < 2; t++) {
        float* ob = out + (size_t)(2 * pair + t) * 8192 + (z * 16) * 256 + col;
        #pragma unroll
        for (int q = 0; q < 4; q++) {
            float f0, f1, f2, f3;
            unpk(yp[t][2 * q],     f0, f1);
            unpk(yp[t][2 * q + 1], f2, f3);
            atomicAdd(ob + (4 * q + 0) * 256, f0);
            atomicAdd(ob + (4 * q + 1) * 256, f1);
            atomicAdd(ob + (4 * q + 2) * 256, f2);
            atomicAdd(ob + (4 * q + 3) * 256, f3);
        }
    }
}

__global__ __launch_bounds__(128)
void tt_bias_kernel(const float* __restrict__ bias, float* __restrict__ out)
{
    // out = 262144 float4 = 128 copies of bias (2048 float4 each); grid 2048
    const int v = blockIdx.x * 128 + threadIdx.x;
    reinterpret_cast<float4*>(out)[v] =
        reinterpret_cast<const float4*>(bias)[v & 2047];
}

extern "C" void kernel_launch(void* const* d_in, const int* in_sizes, int n_in,
                              void* d_out, int out_size)
{
    const float* x    = (const float*)d_in[0];  // [128, 8192]
    const float* g0   = (const float*)d_in[1];  // [1,32,32,4]
    const float* g1   = (const float*)d_in[2];  // [4,16,16,4]
    const float* g2   = (const float*)d_in[3];  // [4,16,16,1]
    const float* bias = (const float*)d_in[4];  // [8192]
    float* out = (float*)d_out;                 // [128, 8192]

    tt_bias_kernel<<<2048, 128>>>(bias, out);
    tt_partial_kernel<<<256, THREADS>>>(x, g0, g1, g2, out);
}